// round 14
// baseline (speedup 1.0000x reference)
#include <cuda_runtime.h>
#include <math.h>

#define NMAX 32
#define BMAX 8
#define LEVELS 6
#define TPB 256
// warp-arrivals per sample: NMAX*LEVELS blocks * (TPB/32) warps
#define ARRIVALS (NMAX * LEVELS * (TPB / 32))
// packed counter: low 20 bits accumulate positive counts, bits >=20 arrivals
#define ARRIVE_UNIT (1u << 20)
#define CNT_MASK    (ARRIVE_UNIT - 1u)

// SIZES computed in double then rounded to f32, matching numpy/jax promotion.
__constant__ float c_UPPER[LEVELS] = {
    (float)(2.23147392 * 22050.0 / 256.0),
    (float)(2.62519274 * 22050.0 / 256.0),
    (float)(3.74199546 * 22050.0 / 256.0),
    (float)(5.78800454 * 22050.0 / 256.0),
    (float)(8.02371882 * 22050.0 / 256.0),
    INFINITY
};
__constant__ float c_LOWER[LEVELS] = {
    0.0f,
    (float)(2.23147392 * 22050.0 / 256.0),
    (float)(2.62519274 * 22050.0 / 256.0),
    (float)(3.74199546 * 22050.0 / 256.0),
    (float)(5.78800454 * 22050.0 / 256.0),
    (float)(8.02371882 * 22050.0 / 256.0)
};

// Persistent accumulators. Zero at module load; the last warp per sample
// resets them, so every graph replay starts clean.
__device__ float    g_loss[BMAX];
__device__ unsigned g_counter[BMAX];

__device__ __forceinline__ float ld_l2(const float* p) {
    float v;
    asm volatile("ld.global.cg.f32 %0, [%1];" : "=f"(v) : "l"(p));
    return v;
}

// ---------------------------------------------------------------------------
// One block per (sample b, ORIGINAL annotation j, level lev); 256 threads.
// Warp-autonomous: no __syncthreads. Winner semantics identical to the
// reference: anchor a belongs to annotation j at level lev iff cand(j,a,lev)
// AND no k with (len_k,k) <lex (len_j,j) also has cand(k,a,lev). All cand
// tests bit-identical to the reference arithmetic; only provably-negative
// work is skipped.
//
// Tail: contributing warps atomicAdd g_loss then __threadfence. EVERY warp
// bumps g_counter[b] by (1<<20)|icnt. The warp whose bump is the last arrival
// recovers the grand count from the SAME atomic's return value (race-free by
// construction) and reads g_loss back through L2 (safe: all other warps'
// fenced adds are visible once their bumps are observed), then resets state.
// ---------------------------------------------------------------------------
__global__ __launch_bounds__(TPB, 1)
void k_fused(const float* __restrict__ ann,
             const float* __restrict__ reg,
             float* __restrict__ out,
             int B, int L0, int A) {
    const int bid  = blockIdx.x;
    const int b    = bid / (NMAX * LEVELS);
    const int rem  = bid % (NMAX * LEVELS);
    const int j    = rem / LEVELS;
    const int lev  = rem % LEVELS;
    const int tid  = threadIdx.x;
    const int lane = tid & 31;

    __shared__ float2 sh_se[NMAX];   // written redundantly by every warp

    // lane k of every warp loads annotation k (2 scalar LDG, L2-hot)
    const int abase = (b * NMAX + lane) * 3;
    const float s_l = ann[abase + 0];
    const float e_l = ann[abase + 1];
    const float len_l = e_l - s_l;

    // benign race: all warps store identical values; each warp only needs
    // its own writes ordered before its own reads -> __syncwarp suffices.
    sh_se[lane] = make_float2(s_l, e_l);
    __syncwarp();

    const float sj   = __shfl_sync(0xFFFFFFFFu, s_l, j);
    const float ej   = __shfl_sync(0xFFFFFFFFu, e_l, j);
    const float lenj = ej - sj;

    const float lower = c_LOWER[lev];
    const float upper = c_UPPER[lev];
    const float scale = (float)(1 << lev);
    const float inv   = 1.0f / scale;

    // possible-blocker mask: k must be lex-smaller and length-compatible with
    // this level band (conservative margins — no true blocker dropped;
    // survivors get the exact test).
    const bool lex  = (len_l < lenj) || (len_l == lenj && lane < j);
    const bool poss = lex && (len_l >= lower - 1.0f) && (len_l * 0.498f < upper);
    const unsigned bmask = __ballot_sync(0xFFFFFFFFu, poss);

    // conservative candidate anchor interval for (j, lev)
    int lo = 1, hi = 0;                     // empty
    if (lenj >= lower) {                    // m <= lenj exactly (monotone fp)
        float lo_pt = fmaxf(sj, ej - upper);   // e - inf -> s
        float hi_pt = fminf(ej, sj + upper);   // s + inf -> e
        int l = (int)floorf(lo_pt * inv - 0.5f) - 2;
        int h = (int)ceilf (hi_pt * inv - 0.5f) + 2;
        const int Li = L0 >> lev;
        l = l < 0 ? 0 : l;
        h = h > Li - 1 ? Li - 1 : h;
        if (l <= h) { lo = l; hi = h; }
    }

    // pyramid row offset of this level
    int off = 0;
    #pragma unroll
    for (int q = 0; q < LEVELS; q++) off += (q < lev) ? (L0 >> q) : 0;
    const float2* regb = (const float2*)reg + (size_t)b * A + off;

    float lsum = 0.0f;
    int   icnt = 0;

    // strip loop: a0 uniform across the block; per-lane validity predicate.
    // TPB=256 -> nearly all intervals (max width ~200) need ONE pass.
    for (int a0 = lo; a0 <= hi; a0 += TPB) {
        const int a = a0 + tid;
        bool contrib = false;

        const float pt = ((float)a + 0.5f) * scale;
        const float l  = pt - sj;
        const float r  = ej - pt;
        const float m  = fmaxf(l, r);
        const bool cand = (a <= hi) & (l >= 0.0f) & (r >= 0.0f) &
                          (m >= lower) & (m < upper);
        if (cand) {
            // issue the regression load now; latency overlaps the scan
            const float2 rb = __ldcg(&regb[a]);

            bool first = true;
            unsigned msk = bmask;
            while (msk) {
                const int k = __ffs(msk) - 1;
                msk &= msk - 1;
                const float2 se = sh_se[k];
                const float l2 = pt - se.x;
                const float r2 = se.y - pt;
                const float m2 = fmaxf(l2, r2);
                if ((l2 >= 0.0f) & (r2 >= 0.0f) &
                    (m2 >= lower) & (m2 < upper)) {
                    first = false;
                    break;
                }
            }

            if (first) {
                const float a0f = pt - l * inv;
                const float a1f = pt + r * inv;
                const float b0  = rb.x, b1 = rb.y;

                float inter = fminf(a1f, b1) - fmaxf(a0f, b0);
                inter = fmaxf(inter, 0.0f);
                const float uni = (a1f - a0f) + (b1 - b0) - inter;
                const float iou = __fdividef(inter, uni + 1e-7f);
                const float enc = fmaxf(a1f, b1) - fminf(a0f, b0);
                float giou = iou - __fdividef(enc - uni, enc + 1e-7f);
                giou = fminf(fmaxf(giou, -1.0f), 1.0f);

                lsum += 1.0f - giou;
                contrib = true;
            }
        }
        // per-warp count via ballot (uniform trip count -> legal)
        icnt += __popc(__ballot_sync(0xFFFFFFFFu, contrib));
    }

    // lsum warp reduce (icnt already warp-total, uniform within warp)
    #pragma unroll
    for (int o = 16; o > 0; o >>= 1)
        lsum += __shfl_down_sync(0xFFFFFFFFu, lsum, o);

    if (lane == 0) {
        if (icnt > 0) {                       // sparse: most warps are empty
            atomicAdd(&g_loss[b], lsum);
            __threadfence();                  // order add before our bump
        }
        // unconditional arrival; count piggybacks on the same atomic
        const unsigned v = atomicAdd(&g_counter[b],
                                     ARRIVE_UNIT + (unsigned)icnt);
        if ((v >> 20) == ARRIVALS - 1) {
            // last arrival: every other warp's fenced loss-add is globally
            // visible; grand count comes from this atomic's return value.
            const float cnt = (float)((v & CNT_MASK) + (unsigned)icnt);
            const float tot = ld_l2(&g_loss[b]);
            out[b] = __fdividef(tot, fmaxf(cnt, 1.0f));
            g_loss[b]    = 0.0f;     // reset for next replay
            g_counter[b] = 0u;
        }
    }
}

// ---------------------------------------------------------------------------
// Launch. Inputs identified by element count (robust to metadata ordering):
//   regressions = max size; class_id = 1; anchors = power-of-two sizes (>1);
//   annotations = the remaining input. B = ann_size / 96.
// ---------------------------------------------------------------------------
extern "C" void kernel_launch(void* const* d_in, const int* in_sizes, int n_in,
                              void* d_out, int out_size) {
    int reg_i = -1;
    long reg_sz = -1;
    for (int i = 0; i < n_in; i++) {
        if ((long)in_sizes[i] > reg_sz) { reg_sz = in_sizes[i]; reg_i = i; }
    }
    int ann_i = -1;
    int L0 = 0;
    for (int i = 0; i < n_in; i++) {
        if (i == reg_i) continue;
        int s = in_sizes[i];
        if (s <= 1) continue;                 // class_id
        bool pow2 = (s & (s - 1)) == 0;
        if (pow2) { if (s > L0) L0 = s; }     // anchors; L0 = largest level
        else       { ann_i = i; }             // annotations (B*32*3, not pow2)
    }

    int B = in_sizes[ann_i] / (NMAX * 3);
    if (B > BMAX) B = BMAX;
    int A = (int)(reg_sz / (2 * B));

    const float* reg = (const float*)d_in[reg_i];
    const float* ann = (const float*)d_in[ann_i];
    float* out = (float*)d_out;

    k_fused<<<B * NMAX * LEVELS, TPB>>>(ann, reg, out, B, L0, A);
}

// round 15
// speedup vs baseline: 1.2642x; 1.2642x over previous
#include <cuda_runtime.h>
#include <math.h>

#define NMAX 32
#define BMAX 8
#define LEVELS 6
#define TPB 128
// warp-arrivals per sample: NMAX*LEVELS blocks * (TPB/32) warps
#define ARRIVALS (NMAX * LEVELS * (TPB / 32))

// single packed accumulator per sample:
//   bits [0:38)  loss sum, fixed point scale 2^20  (max ~2^18 loss units)
//   bits [38:52) positive-anchor count             (max 16383)
//   bits [52:64) warp arrivals                     (max 4095)
#define LOSS_BITS 38
#define CNT_BITS  14
#define LOSS_MASK ((1ULL << LOSS_BITS) - 1ULL)
#define CNT_MASK  ((1ULL << CNT_BITS) - 1ULL)
#define ARRIVE_ONE (1ULL << (LOSS_BITS + CNT_BITS))
#define LOSS_SCALE 1048576.0f            // 2^20
#define LOSS_INV   (1.0f / 1048576.0f)

// SIZES computed in double then rounded to f32, matching numpy/jax promotion.
__constant__ float c_UPPER[LEVELS] = {
    (float)(2.23147392 * 22050.0 / 256.0),
    (float)(2.62519274 * 22050.0 / 256.0),
    (float)(3.74199546 * 22050.0 / 256.0),
    (float)(5.78800454 * 22050.0 / 256.0),
    (float)(8.02371882 * 22050.0 / 256.0),
    INFINITY
};
__constant__ float c_LOWER[LEVELS] = {
    0.0f,
    (float)(2.23147392 * 22050.0 / 256.0),
    (float)(2.62519274 * 22050.0 / 256.0),
    (float)(3.74199546 * 22050.0 / 256.0),
    (float)(5.78800454 * 22050.0 / 256.0),
    (float)(8.02371882 * 22050.0 / 256.0)
};

// Persistent accumulator. Zero at module load; the last warp per sample
// resets it, so every graph replay starts clean.
__device__ unsigned long long g_acc[BMAX];

// ---------------------------------------------------------------------------
// One block per (sample b, ORIGINAL annotation j, level lev); 128 threads.
// Warp-autonomous: no __syncthreads. Winner semantics identical to the
// reference: anchor a belongs to annotation j at level lev iff cand(j,a,lev)
// AND no k with (len_k,k) <lex (len_j,j) also has cand(k,a,lev). All cand
// tests are bit-identical to the reference arithmetic; only provably-negative
// work is skipped.
//
// Tail: ONE 64-bit atomic per warp carries (arrival, count, fixed-point loss)
// together. The warp whose bump is the last arrival reconstructs the grand
// totals from the SAME atomic's return value + its own addend — race-free by
// construction (no second address, hence no fence and no readback).
// ---------------------------------------------------------------------------
__global__ __launch_bounds__(TPB, 1)
void k_fused(const float* __restrict__ ann,
             const float* __restrict__ reg,
             float* __restrict__ out,
             int B, int L0, int A) {
    const int bid  = blockIdx.x;
    const int b    = bid / (NMAX * LEVELS);
    const int rem  = bid % (NMAX * LEVELS);
    const int j    = rem / LEVELS;
    const int lev  = rem % LEVELS;
    const int tid  = threadIdx.x;
    const int lane = tid & 31;

    __shared__ float2 sh_se[NMAX];   // written redundantly by every warp

    // lane k of every warp loads annotation k (2 scalar LDG, L2-hot)
    const int abase = (b * NMAX + lane) * 3;
    const float s_l = ann[abase + 0];
    const float e_l = ann[abase + 1];
    const float len_l = e_l - s_l;

    // benign race: all warps store identical values; each warp only needs
    // its own writes ordered before its own reads -> __syncwarp suffices.
    sh_se[lane] = make_float2(s_l, e_l);
    __syncwarp();

    const float sj   = __shfl_sync(0xFFFFFFFFu, s_l, j);
    const float ej   = __shfl_sync(0xFFFFFFFFu, e_l, j);
    const float lenj = ej - sj;

    const float lower = c_LOWER[lev];
    const float upper = c_UPPER[lev];
    const float scale = (float)(1 << lev);
    const float inv   = 1.0f / scale;

    // possible-blocker mask: k must be lex-smaller and length-compatible with
    // this level band (conservative margins — no true blocker dropped;
    // survivors get the exact test).
    const bool lex  = (len_l < lenj) || (len_l == lenj && lane < j);
    const bool poss = lex && (len_l >= lower - 1.0f) && (len_l * 0.498f < upper);
    const unsigned bmask = __ballot_sync(0xFFFFFFFFu, poss);

    // conservative candidate anchor interval for (j, lev)
    int lo = 1, hi = 0;                     // empty
    if (lenj >= lower) {                    // m <= lenj exactly (monotone fp)
        float lo_pt = fmaxf(sj, ej - upper);   // e - inf -> s
        float hi_pt = fminf(ej, sj + upper);   // s + inf -> e
        int l = (int)floorf(lo_pt * inv - 0.5f) - 2;
        int h = (int)ceilf (hi_pt * inv - 0.5f) + 2;
        const int Li = L0 >> lev;
        l = l < 0 ? 0 : l;
        h = h > Li - 1 ? Li - 1 : h;
        if (l <= h) { lo = l; hi = h; }
    }

    // pyramid row offset of this level
    int off = 0;
    #pragma unroll
    for (int q = 0; q < LEVELS; q++) off += (q < lev) ? (L0 >> q) : 0;
    const float2* regb = (const float2*)reg + (size_t)b * A + off;

    float lsum = 0.0f;
    int   icnt = 0;

    // strip loop: a0 uniform across the block; per-lane validity predicate
    for (int a0 = lo; a0 <= hi; a0 += TPB) {
        const int a = a0 + tid;
        bool contrib = false;

        const float pt = ((float)a + 0.5f) * scale;
        const float l  = pt - sj;
        const float r  = ej - pt;
        const float m  = fmaxf(l, r);
        const bool cand = (a <= hi) & (l >= 0.0f) & (r >= 0.0f) &
                          (m >= lower) & (m < upper);
        if (cand) {
            // issue the regression load now; latency overlaps the scan
            const float2 rb = __ldcg(&regb[a]);

            bool first = true;
            unsigned msk = bmask;
            while (msk) {
                const int k = __ffs(msk) - 1;
                msk &= msk - 1;
                const float2 se = sh_se[k];
                const float l2 = pt - se.x;
                const float r2 = se.y - pt;
                const float m2 = fmaxf(l2, r2);
                if ((l2 >= 0.0f) & (r2 >= 0.0f) &
                    (m2 >= lower) & (m2 < upper)) {
                    first = false;
                    break;
                }
            }

            if (first) {
                const float a0f = pt - l * inv;
                const float a1f = pt + r * inv;
                const float b0  = rb.x, b1 = rb.y;

                float inter = fminf(a1f, b1) - fmaxf(a0f, b0);
                inter = fmaxf(inter, 0.0f);
                const float uni = (a1f - a0f) + (b1 - b0) - inter;
                const float iou = __fdividef(inter, uni + 1e-7f);
                const float enc = fmaxf(a1f, b1) - fminf(a0f, b0);
                float giou = iou - __fdividef(enc - uni, enc + 1e-7f);
                giou = fminf(fmaxf(giou, -1.0f), 1.0f);

                lsum += 1.0f - giou;
                contrib = true;
            }
        }
        // per-warp count via ballot (uniform trip count -> legal)
        icnt += __popc(__ballot_sync(0xFFFFFFFFu, contrib));
    }

    // lsum warp reduce (icnt already warp-total, uniform within warp)
    #pragma unroll
    for (int o = 16; o > 0; o >>= 1)
        lsum += __shfl_down_sync(0xFFFFFFFFu, lsum, o);

    if (lane == 0) {
        // pack (arrival=1, count=icnt, loss=round(lsum * 2^20))
        const unsigned long long addv =
            ARRIVE_ONE
            | ((unsigned long long)(unsigned)icnt << LOSS_BITS)
            | (unsigned long long)__float2ull_rn(lsum * LOSS_SCALE);
        const unsigned long long old = atomicAdd(&g_acc[b], addv);
        if ((old >> (LOSS_BITS + CNT_BITS)) ==
            (unsigned long long)(ARRIVALS - 1)) {
            // last arrival: totals = old + my addend (single-address, exact)
            const unsigned long long tot = old + addv;
            const float cnt  = (float)((tot >> LOSS_BITS) & CNT_MASK);
            const float loss = (float)(tot & LOSS_MASK) * LOSS_INV;
            out[b] = __fdividef(loss, fmaxf(cnt, 1.0f));
            g_acc[b] = 0ULL;                 // reset for next replay
        }
    }
}

// ---------------------------------------------------------------------------
// Launch. Inputs identified by element count (robust to metadata ordering):
//   regressions = max size; class_id = 1; anchors = power-of-two sizes (>1);
//   annotations = the remaining input. B = ann_size / 96.
// ---------------------------------------------------------------------------
extern "C" void kernel_launch(void* const* d_in, const int* in_sizes, int n_in,
                              void* d_out, int out_size) {
    int reg_i = -1;
    long reg_sz = -1;
    for (int i = 0; i < n_in; i++) {
        if ((long)in_sizes[i] > reg_sz) { reg_sz = in_sizes[i]; reg_i = i; }
    }
    int ann_i = -1;
    int L0 = 0;
    for (int i = 0; i < n_in; i++) {
        if (i == reg_i) continue;
        int s = in_sizes[i];
        if (s <= 1) continue;                 // class_id
        bool pow2 = (s & (s - 1)) == 0;
        if (pow2) { if (s > L0) L0 = s; }     // anchors; L0 = largest level
        else       { ann_i = i; }             // annotations (B*32*3, not pow2)
    }

    int B = in_sizes[ann_i] / (NMAX * 3);
    if (B > BMAX) B = BMAX;
    int A = (int)(reg_sz / (2 * B));

    const float* reg = (const float*)d_in[reg_i];
    const float* ann = (const float*)d_in[ann_i];
    float* out = (float*)d_out;

    k_fused<<<B * NMAX * LEVELS, TPB>>>(ann, reg, out, B, L0, A);
}